// round 3
// baseline (speedup 1.0000x reference)
#include <cuda_runtime.h>
#include <math.h>

#define D 128
#define H 4
#define NMAX 500000
#define BMAX 8192
#define ROWS_CAP 128

// Scratch: seg starts always; g_scores only used by the (never-in-practice)
// long-segment fallback path.
__device__ float4 g_scores[NMAX];
__device__ int    g_seg_start[BMAX + 1];

// ---------------------------------------------------------------------------
// Dtype-agnostic ids (reference claims int64 but JAX x64-off gives int32).
// ---------------------------------------------------------------------------
__device__ __forceinline__ bool ids_are_64bit(const int* ids32, int N) {
    int j = ((N - 1) & 1) ? (N - 1) : (N - 2);
    if (j < 0) j = 0;
    return ids32[j] == 0;   // high word of small int64 == 0; late int32 id != 0
}
__device__ __forceinline__ int get_id(const void* ids, bool is64, int n, int B) {
    int v = is64 ? (int)((const long long*)ids)[n] : ((const int*)ids)[n];
    return v < 0 ? 0 : (v >= B ? B - 1 : v);
}

// ---------------------------------------------------------------------------
// Kernel 0: segment boundaries. 4 ids per thread.
// ---------------------------------------------------------------------------
__global__ void k_bounds(const void* __restrict__ ids, int N, int B) {
    int base = (blockIdx.x * blockDim.x + threadIdx.x) * 4;
    if (base >= N) return;
    bool is64 = ids_are_64bit((const int*)ids, N);
    int prev = (base == 0) ? -1 : get_id(ids, is64, base - 1, B);
    #pragma unroll
    for (int k = 0; k < 4; k++) {
        int n = base + k;
        if (n >= N) break;
        int id = get_id(ids, is64, n, B);
        if (n == 0) {
            for (int bb = 0; bb <= id; bb++) g_seg_start[bb] = 0;
        } else {
            for (int bb = prev + 1; bb <= id; bb++) g_seg_start[bb] = n;
        }
        if (n == N - 1) {
            for (int bb = id + 1; bb <= B; bb++) g_seg_start[bb] = N;
        }
        prev = id;
    }
}

// ---------------------------------------------------------------------------
// Fused kernel: one block (128 threads) per segment.
//   fast path (len <= ROWS_CAP): x segment cached in smem; single HBM read.
//   slow path: global-memory fallback (statistically never taken).
// Dynamic smem layout (floats):
//   xs   [ROWS_CAP*128]  segment rows, row stride 128 floats
//   sc_s [ROWS_CAP*4]    per-node head scores (float4)
//   w_s  [ROWS_CAP]      per-node mean attention weight
//   wred [4*4]           cross-warp reduction scratch (float4)
// ---------------------------------------------------------------------------
__global__ void __launch_bounds__(128) k_fused(
    const float* __restrict__ x,
    const float* __restrict__ W,
    const float* __restrict__ bias,
    const float* __restrict__ temp,
    float* __restrict__ out_pooled,   // [B, D]
    float* __restrict__ out_attn,     // [H, N]
    int N)
{
    extern __shared__ float sdyn[];
    float*  xs   = sdyn;
    float4* sc_s = (float4*)(sdyn + ROWS_CAP * 128);
    float*  w_s  = sdyn + ROWS_CAP * 128 + ROWS_CAP * 4;
    float4* wred = (float4*)(sdyn + ROWS_CAP * 128 + ROWS_CAP * 4 + ROWS_CAP);

    int b     = blockIdx.x;
    int start = g_seg_start[b];
    int end   = g_seg_start[b + 1];
    int len   = end - start;
    int tid   = threadIdx.x;
    int lane  = tid & 31, warp = tid >> 5;

    // Per-lane W slice (L1/L2-hot, 2 KB total) + bias + 1/T
    float4 w0 = ((const float4*)W)[lane];
    float4 w1 = ((const float4*)W)[32 + lane];
    float4 w2 = ((const float4*)W)[64 + lane];
    float4 w3 = ((const float4*)W)[96 + lane];
    float4 bv = *(const float4*)bias;
    float  tinv = 1.0f / temp[0];

    if (len <= ROWS_CAP) {
        // ---- load segment x into smem (coalesced float4) ----
        const float4* xg  = (const float4*)(x + (size_t)start * D);
        float4*       xs4 = (float4*)xs;
        int tot = len * (D / 4);
        for (int i = tid; i < tot; i += 128) xs4[i] = xg[i];
        __syncthreads();

        // ---- scores: warp per node from smem ----
        for (int n = warp; n < len; n += 4) {
            float4 xv = ((float4*)(xs + n * D))[lane];
            float s0 = xv.x * w0.x + xv.y * w0.y + xv.z * w0.z + xv.w * w0.w;
            float s1 = xv.x * w1.x + xv.y * w1.y + xv.z * w1.z + xv.w * w1.w;
            float s2 = xv.x * w2.x + xv.y * w2.y + xv.z * w2.z + xv.w * w2.w;
            float s3 = xv.x * w3.x + xv.y * w3.y + xv.z * w3.z + xv.w * w3.w;
            #pragma unroll
            for (int off = 16; off > 0; off >>= 1) {
                s0 += __shfl_xor_sync(0xFFFFFFFFu, s0, off);
                s1 += __shfl_xor_sync(0xFFFFFFFFu, s1, off);
                s2 += __shfl_xor_sync(0xFFFFFFFFu, s2, off);
                s3 += __shfl_xor_sync(0xFFFFFFFFu, s3, off);
            }
            if (lane == 0) {
                float4 sc;
                sc.x = (s0 + bv.x) * tinv;
                sc.y = (s1 + bv.y) * tinv;
                sc.z = (s2 + bv.z) * tinv;
                sc.w = (s3 + bv.w) * tinv;
                sc_s[n] = sc;
            }
        }
        __syncthreads();

        // ---- softmax stats: each thread owns <=1 node ----
        float4 sv = (tid < len) ? sc_s[tid]
                                : make_float4(-INFINITY, -INFINITY, -INFINITY, -INFINITY);
        float4 m = sv;
        #pragma unroll
        for (int off = 16; off > 0; off >>= 1) {
            m.x = fmaxf(m.x, __shfl_xor_sync(0xFFFFFFFFu, m.x, off));
            m.y = fmaxf(m.y, __shfl_xor_sync(0xFFFFFFFFu, m.y, off));
            m.z = fmaxf(m.z, __shfl_xor_sync(0xFFFFFFFFu, m.z, off));
            m.w = fmaxf(m.w, __shfl_xor_sync(0xFFFFFFFFu, m.w, off));
        }
        if (lane == 0) wred[warp] = m;
        __syncthreads();
        float4 M;
        {
            float4 a = wred[0], c = wred[1], e = wred[2], g = wred[3];
            M.x = fmaxf(fmaxf(a.x, c.x), fmaxf(e.x, g.x));
            M.y = fmaxf(fmaxf(a.y, c.y), fmaxf(e.y, g.y));
            M.z = fmaxf(fmaxf(a.z, c.z), fmaxf(e.z, g.z));
            M.w = fmaxf(fmaxf(a.w, c.w), fmaxf(e.w, g.w));
        }
        __syncthreads();

        float e0 = 0.f, e1 = 0.f, e2 = 0.f, e3 = 0.f;
        if (tid < len) {
            e0 = __expf(sv.x - M.x); e1 = __expf(sv.y - M.y);
            e2 = __expf(sv.z - M.z); e3 = __expf(sv.w - M.w);
        }
        float4 s4 = make_float4(e0, e1, e2, e3);
        #pragma unroll
        for (int off = 16; off > 0; off >>= 1) {
            s4.x += __shfl_xor_sync(0xFFFFFFFFu, s4.x, off);
            s4.y += __shfl_xor_sync(0xFFFFFFFFu, s4.y, off);
            s4.z += __shfl_xor_sync(0xFFFFFFFFu, s4.z, off);
            s4.w += __shfl_xor_sync(0xFFFFFFFFu, s4.w, off);
        }
        if (lane == 0) wred[warp] = s4;
        __syncthreads();
        float4 R;
        {
            float4 a = wred[0], c = wred[1], e = wred[2], g = wred[3];
            float sx = a.x + c.x + e.x + g.x;
            float sy = a.y + c.y + e.y + g.y;
            float sz = a.z + c.z + e.z + g.z;
            float sw = a.w + c.w + e.w + g.w;
            R.x = (len > 0) ? 1.0f / sx : 0.f;
            R.y = (len > 0) ? 1.0f / sy : 0.f;
            R.z = (len > 0) ? 1.0f / sz : 0.f;
            R.w = (len > 0) ? 1.0f / sw : 0.f;
        }

        // ---- attn output (coalesced per head) + per-node weight ----
        if (tid < len) {
            float a0 = e0 * R.x, a1 = e1 * R.y, a2 = e2 * R.z, a3 = e3 * R.w;
            size_t p = (size_t)start + tid;
            out_attn[p]              = a0;
            out_attn[(size_t)N + p]  = a1;
            out_attn[2 * (size_t)N + p] = a2;
            out_attn[3 * (size_t)N + p] = a3;
            w_s[tid] = 0.25f * (a0 + a1 + a2 + a3);
        }
        __syncthreads();

        // ---- pooled from smem: thread t owns dim t ----
        float acc0 = 0.f, acc1 = 0.f, acc2 = 0.f, acc3 = 0.f;
        int j = 0;
        for (; j + 4 <= len; j += 4) {
            acc0 += w_s[j + 0] * xs[(j + 0) * D + tid];
            acc1 += w_s[j + 1] * xs[(j + 1) * D + tid];
            acc2 += w_s[j + 2] * xs[(j + 2) * D + tid];
            acc3 += w_s[j + 3] * xs[(j + 3) * D + tid];
        }
        for (; j < len; j++) acc0 += w_s[j] * xs[j * D + tid];
        out_pooled[(size_t)b * D + tid] = (acc0 + acc1) + (acc2 + acc3);
        return;
    }

    // ======================= slow fallback (len > ROWS_CAP) ==================
    // scores -> global scratch
    for (int n = warp; n < len; n += 4) {
        float4 xv = ((const float4*)(x + (size_t)(start + n) * D))[lane];
        float s0 = xv.x * w0.x + xv.y * w0.y + xv.z * w0.z + xv.w * w0.w;
        float s1 = xv.x * w1.x + xv.y * w1.y + xv.z * w1.z + xv.w * w1.w;
        float s2 = xv.x * w2.x + xv.y * w2.y + xv.z * w2.z + xv.w * w2.w;
        float s3 = xv.x * w3.x + xv.y * w3.y + xv.z * w3.z + xv.w * w3.w;
        #pragma unroll
        for (int off = 16; off > 0; off >>= 1) {
            s0 += __shfl_xor_sync(0xFFFFFFFFu, s0, off);
            s1 += __shfl_xor_sync(0xFFFFFFFFu, s1, off);
            s2 += __shfl_xor_sync(0xFFFFFFFFu, s2, off);
            s3 += __shfl_xor_sync(0xFFFFFFFFu, s3, off);
        }
        if (lane == 0) {
            float4 sc;
            sc.x = (s0 + bv.x) * tinv; sc.y = (s1 + bv.y) * tinv;
            sc.z = (s2 + bv.z) * tinv; sc.w = (s3 + bv.w) * tinv;
            g_scores[start + n] = sc;
        }
    }
    __syncthreads();

    float4 m = make_float4(-INFINITY, -INFINITY, -INFINITY, -INFINITY);
    for (int i = tid; i < len; i += 128) {
        float4 s = g_scores[start + i];
        m.x = fmaxf(m.x, s.x); m.y = fmaxf(m.y, s.y);
        m.z = fmaxf(m.z, s.z); m.w = fmaxf(m.w, s.w);
    }
    #pragma unroll
    for (int off = 16; off > 0; off >>= 1) {
        m.x = fmaxf(m.x, __shfl_xor_sync(0xFFFFFFFFu, m.x, off));
        m.y = fmaxf(m.y, __shfl_xor_sync(0xFFFFFFFFu, m.y, off));
        m.z = fmaxf(m.z, __shfl_xor_sync(0xFFFFFFFFu, m.z, off));
        m.w = fmaxf(m.w, __shfl_xor_sync(0xFFFFFFFFu, m.w, off));
    }
    if (lane == 0) wred[warp] = m;
    __syncthreads();
    float4 M;
    {
        float4 a = wred[0], c = wred[1], e = wred[2], g = wred[3];
        M.x = fmaxf(fmaxf(a.x, c.x), fmaxf(e.x, g.x));
        M.y = fmaxf(fmaxf(a.y, c.y), fmaxf(e.y, g.y));
        M.z = fmaxf(fmaxf(a.z, c.z), fmaxf(e.z, g.z));
        M.w = fmaxf(fmaxf(a.w, c.w), fmaxf(e.w, g.w));
    }
    __syncthreads();

    float4 sum = make_float4(0.f, 0.f, 0.f, 0.f);
    for (int i = tid; i < len; i += 128) {
        float4 s = g_scores[start + i];
        sum.x += __expf(s.x - M.x); sum.y += __expf(s.y - M.y);
        sum.z += __expf(s.z - M.z); sum.w += __expf(s.w - M.w);
    }
    #pragma unroll
    for (int off = 16; off > 0; off >>= 1) {
        sum.x += __shfl_xor_sync(0xFFFFFFFFu, sum.x, off);
        sum.y += __shfl_xor_sync(0xFFFFFFFFu, sum.y, off);
        sum.z += __shfl_xor_sync(0xFFFFFFFFu, sum.z, off);
        sum.w += __shfl_xor_sync(0xFFFFFFFFu, sum.w, off);
    }
    if (lane == 0) wred[warp] = sum;
    __syncthreads();
    float4 R;
    {
        float4 a = wred[0], c = wred[1], e = wred[2], g = wred[3];
        R.x = 1.0f / (a.x + c.x + e.x + g.x);
        R.y = 1.0f / (a.y + c.y + e.y + g.y);
        R.z = 1.0f / (a.z + c.z + e.z + g.z);
        R.w = 1.0f / (a.w + c.w + e.w + g.w);
    }

    float acc = 0.f;
    for (int c = 0; c < len; c += 128) {
        int cl = min(128, len - c);
        __syncthreads();
        if (tid < cl) {
            float4 s = g_scores[start + c + tid];
            float a0 = __expf(s.x - M.x) * R.x;
            float a1 = __expf(s.y - M.y) * R.y;
            float a2 = __expf(s.z - M.z) * R.z;
            float a3 = __expf(s.w - M.w) * R.w;
            size_t p = (size_t)start + c + tid;
            out_attn[p] = a0;
            out_attn[(size_t)N + p] = a1;
            out_attn[2 * (size_t)N + p] = a2;
            out_attn[3 * (size_t)N + p] = a3;
            w_s[tid] = 0.25f * (a0 + a1 + a2 + a3);
        }
        __syncthreads();
        const float* xb = x + (size_t)(start + c) * D + tid;
        for (int j = 0; j < cl; j++) acc += w_s[j] * xb[(size_t)j * D];
    }
    out_pooled[(size_t)b * D + tid] = acc;
}

// ---------------------------------------------------------------------------
extern "C" void kernel_launch(void* const* d_in, const int* in_sizes, int n_in,
                              void* d_out, int out_size)
{
    const float* x    = (const float*)d_in[0];
    const void*  ids  = d_in[1];
    const float* W    = (const float*)d_in[2];
    const float* bias = (const float*)d_in[3];
    const float* temp = (const float*)d_in[4];

    int N = in_sizes[1];
    int B = (out_size - H * N) / D;
    if (B < 1) B = 1;
    if (B > BMAX) B = BMAX;

    float* out_pooled = (float*)d_out;                   // [B, D]
    float* out_attn   = (float*)d_out + (size_t)B * D;   // [H, N]

    const int SMEM = (ROWS_CAP * 128 + ROWS_CAP * 4 + ROWS_CAP + 16) * 4;
    cudaFuncSetAttribute(k_fused, cudaFuncAttributeMaxDynamicSharedMemorySize, SMEM);

    k_bounds<<<(N / 4 + 256) / 256 + 1, 256>>>(ids, N, B);
    k_fused<<<B, 128, SMEM>>>(x, W, bias, temp, out_pooled, out_attn, N);
}

// round 4
// speedup vs baseline: 1.2653x; 1.2653x over previous
#include <cuda_runtime.h>
#include <math.h>

#define D 128
#define H 4
#define NMAX 500000
#define BMAX 8192
#define ROWS_CAP 96
#define NT 256          // threads per block (8 warps)

// Global scratch (fallback path only) + segment starts.
__device__ float4 g_scores[NMAX];
__device__ int    g_seg_start[BMAX + 1];

// ---------------------------------------------------------------------------
// Dtype-agnostic ids (reference claims int64 but JAX x64-off gives int32).
// ---------------------------------------------------------------------------
__device__ __forceinline__ bool ids_are_64bit(const int* ids32, int N) {
    int j = ((N - 1) & 1) ? (N - 1) : (N - 2);
    if (j < 0) j = 0;
    return ids32[j] == 0;   // high word of small int64 == 0; late int32 id != 0
}
__device__ __forceinline__ int get_id_raw(const void* ids, bool is64, int n) {
    return is64 ? (int)((const long long*)ids)[n] : ((const int*)ids)[n];
}

// ---------------------------------------------------------------------------
// Kernel 0: seg_start[b] = lower_bound(ids, b). One thread per boundary.
// 19 dependent L2-hot probes each; 8193 threads -> fully parallel.
// ---------------------------------------------------------------------------
__global__ void k_bounds(const void* __restrict__ ids, int N, int B) {
    int b = blockIdx.x * blockDim.x + threadIdx.x;
    if (b > B) return;
    bool is64 = ids_are_64bit((const int*)ids, N);
    int lo = 0, hi = N;
    while (lo < hi) {
        int mid = (lo + hi) >> 1;
        if (get_id_raw(ids, is64, mid) < b) lo = mid + 1; else hi = mid;
    }
    g_seg_start[b] = lo;
}

// ---------------------------------------------------------------------------
// Fused kernel: one block (256 threads) per segment.
// Dynamic smem (floats):
//   xs   [ROWS_CAP*128] segment rows          (offset 0)
//   sc_s [ROWS_CAP*4]   per-node head scores  (offset 12288)
//   w_s  [256]          per-node mean weight  (offset 12672)
//   pred [128]          pooling phase-reduce  (offset 12928)
//   wred [8*4]          warp-reduce scratch   (offset 13056)
// total 13088 floats = 52352 B -> 4 blocks/SM.
// ---------------------------------------------------------------------------
__global__ void __launch_bounds__(NT, 4) k_fused(
    const float* __restrict__ x,
    const float* __restrict__ W,
    const float* __restrict__ bias,
    const float* __restrict__ temp,
    float* __restrict__ out_pooled,   // [B, D]
    float* __restrict__ out_attn,     // [H, N]
    int N)
{
    extern __shared__ float sdyn[];
    float*  xs   = sdyn;
    float4* sc_s = (float4*)(sdyn + ROWS_CAP * 128);
    float*  w_s  = sdyn + ROWS_CAP * 128 + ROWS_CAP * 4;
    float*  pred = w_s + 256;
    float4* wred = (float4*)(pred + 128);

    int b     = blockIdx.x;
    int start = g_seg_start[b];
    int end   = g_seg_start[b + 1];
    int len   = end - start;
    int tid   = threadIdx.x;
    int lane  = tid & 31, warp = tid >> 5;
    int phase = tid >> 7;      // 0/1: row-group for pooling
    int dd    = tid & 127;     // owned output dim

    // W rows per lane (L1-hot 2 KB) + bias + 1/T
    float4 w0 = ((const float4*)W)[lane];
    float4 w1 = ((const float4*)W)[32 + lane];
    float4 w2 = ((const float4*)W)[64 + lane];
    float4 w3 = ((const float4*)W)[96 + lane];
    float4 bv = *(const float4*)bias;
    float  tinv = 1.0f / temp[0];

    if (len <= ROWS_CAP) {
        // ---- load segment x into smem (coalesced float4) ----
        const float4* xg  = (const float4*)(x + (size_t)start * D);
        float4*       xs4 = (float4*)xs;
        int tot = len * (D / 4);
        for (int i = tid; i < tot; i += NT) xs4[i] = xg[i];
        __syncthreads();

        // ---- scores: warp per node (8 warps) ----
        for (int n = warp; n < len; n += 8) {
            float4 xv = ((float4*)(xs + n * D))[lane];
            float s0 = xv.x * w0.x + xv.y * w0.y + xv.z * w0.z + xv.w * w0.w;
            float s1 = xv.x * w1.x + xv.y * w1.y + xv.z * w1.z + xv.w * w1.w;
            float s2 = xv.x * w2.x + xv.y * w2.y + xv.z * w2.z + xv.w * w2.w;
            float s3 = xv.x * w3.x + xv.y * w3.y + xv.z * w3.z + xv.w * w3.w;
            #pragma unroll
            for (int off = 16; off > 0; off >>= 1) {
                s0 += __shfl_xor_sync(0xFFFFFFFFu, s0, off);
                s1 += __shfl_xor_sync(0xFFFFFFFFu, s1, off);
                s2 += __shfl_xor_sync(0xFFFFFFFFu, s2, off);
                s3 += __shfl_xor_sync(0xFFFFFFFFu, s3, off);
            }
            if (lane == 0) {
                float4 sc;
                sc.x = (s0 + bv.x) * tinv;
                sc.y = (s1 + bv.y) * tinv;
                sc.z = (s2 + bv.z) * tinv;
                sc.w = (s3 + bv.w) * tinv;
                sc_s[n] = sc;
            }
        }
        __syncthreads();

        // ---- softmax stats: thread owns <=1 node (len <= 96 < 256) ----
        float4 sv = (tid < len) ? sc_s[tid]
                                : make_float4(-INFINITY, -INFINITY, -INFINITY, -INFINITY);
        float4 m = sv;
        #pragma unroll
        for (int off = 16; off > 0; off >>= 1) {
            m.x = fmaxf(m.x, __shfl_xor_sync(0xFFFFFFFFu, m.x, off));
            m.y = fmaxf(m.y, __shfl_xor_sync(0xFFFFFFFFu, m.y, off));
            m.z = fmaxf(m.z, __shfl_xor_sync(0xFFFFFFFFu, m.z, off));
            m.w = fmaxf(m.w, __shfl_xor_sync(0xFFFFFFFFu, m.w, off));
        }
        if (lane == 0) wred[warp] = m;
        __syncthreads();
        float4 M;
        {
            float4 r0 = wred[0];
            #pragma unroll
            for (int wi = 1; wi < 8; wi++) {
                float4 t = wred[wi];
                r0.x = fmaxf(r0.x, t.x); r0.y = fmaxf(r0.y, t.y);
                r0.z = fmaxf(r0.z, t.z); r0.w = fmaxf(r0.w, t.w);
            }
            M = r0;
        }
        __syncthreads();

        float e0 = 0.f, e1 = 0.f, e2 = 0.f, e3 = 0.f;
        if (tid < len) {
            e0 = __expf(sv.x - M.x); e1 = __expf(sv.y - M.y);
            e2 = __expf(sv.z - M.z); e3 = __expf(sv.w - M.w);
        }
        float4 s4 = make_float4(e0, e1, e2, e3);
        #pragma unroll
        for (int off = 16; off > 0; off >>= 1) {
            s4.x += __shfl_xor_sync(0xFFFFFFFFu, s4.x, off);
            s4.y += __shfl_xor_sync(0xFFFFFFFFu, s4.y, off);
            s4.z += __shfl_xor_sync(0xFFFFFFFFu, s4.z, off);
            s4.w += __shfl_xor_sync(0xFFFFFFFFu, s4.w, off);
        }
        if (lane == 0) wred[warp] = s4;
        __syncthreads();
        float4 R;
        {
            float4 r0 = wred[0];
            #pragma unroll
            for (int wi = 1; wi < 8; wi++) {
                float4 t = wred[wi];
                r0.x += t.x; r0.y += t.y; r0.z += t.z; r0.w += t.w;
            }
            R.x = (len > 0) ? 1.0f / r0.x : 0.f;
            R.y = (len > 0) ? 1.0f / r0.y : 0.f;
            R.z = (len > 0) ? 1.0f / r0.z : 0.f;
            R.w = (len > 0) ? 1.0f / r0.w : 0.f;
        }

        // ---- attn output + per-node mean weight ----
        if (tid < len) {
            float a0 = e0 * R.x, a1 = e1 * R.y, a2 = e2 * R.z, a3 = e3 * R.w;
            size_t p = (size_t)start + tid;
            out_attn[p]                 = a0;
            out_attn[(size_t)N + p]     = a1;
            out_attn[2 * (size_t)N + p] = a2;
            out_attn[3 * (size_t)N + p] = a3;
            w_s[tid] = 0.25f * (a0 + a1 + a2 + a3);
        }
        __syncthreads();

        // ---- pooled from smem: 2 row-groups x 128 dims, 4-way unroll ----
        float a0 = 0.f, a1 = 0.f, a2 = 0.f, a3 = 0.f;
        int j = phase;
        for (; j + 6 < len; j += 8) {
            a0 += w_s[j]     * xs[j * D + dd];
            a1 += w_s[j + 2] * xs[(j + 2) * D + dd];
            a2 += w_s[j + 4] * xs[(j + 4) * D + dd];
            a3 += w_s[j + 6] * xs[(j + 6) * D + dd];
        }
        for (; j < len; j += 2) a0 += w_s[j] * xs[j * D + dd];
        float acc = (a0 + a1) + (a2 + a3);
        if (phase == 1) pred[dd] = acc;
        __syncthreads();
        if (phase == 0) out_pooled[(size_t)b * D + dd] = acc + pred[dd];
        return;
    }

    // ======================= fallback (len > ROWS_CAP) =======================
    for (int n = warp; n < len; n += 8) {
        float4 xv = ((const float4*)(x + (size_t)(start + n) * D))[lane];
        float s0 = xv.x * w0.x + xv.y * w0.y + xv.z * w0.z + xv.w * w0.w;
        float s1 = xv.x * w1.x + xv.y * w1.y + xv.z * w1.z + xv.w * w1.w;
        float s2 = xv.x * w2.x + xv.y * w2.y + xv.z * w2.z + xv.w * w2.w;
        float s3 = xv.x * w3.x + xv.y * w3.y + xv.z * w3.z + xv.w * w3.w;
        #pragma unroll
        for (int off = 16; off > 0; off >>= 1) {
            s0 += __shfl_xor_sync(0xFFFFFFFFu, s0, off);
            s1 += __shfl_xor_sync(0xFFFFFFFFu, s1, off);
            s2 += __shfl_xor_sync(0xFFFFFFFFu, s2, off);
            s3 += __shfl_xor_sync(0xFFFFFFFFu, s3, off);
        }
        if (lane == 0) {
            float4 sc;
            sc.x = (s0 + bv.x) * tinv; sc.y = (s1 + bv.y) * tinv;
            sc.z = (s2 + bv.z) * tinv; sc.w = (s3 + bv.w) * tinv;
            g_scores[start + n] = sc;
        }
    }
    __syncthreads();

    float4 m = make_float4(-INFINITY, -INFINITY, -INFINITY, -INFINITY);
    for (int i = tid; i < len; i += NT) {
        float4 s = g_scores[start + i];
        m.x = fmaxf(m.x, s.x); m.y = fmaxf(m.y, s.y);
        m.z = fmaxf(m.z, s.z); m.w = fmaxf(m.w, s.w);
    }
    #pragma unroll
    for (int off = 16; off > 0; off >>= 1) {
        m.x = fmaxf(m.x, __shfl_xor_sync(0xFFFFFFFFu, m.x, off));
        m.y = fmaxf(m.y, __shfl_xor_sync(0xFFFFFFFFu, m.y, off));
        m.z = fmaxf(m.z, __shfl_xor_sync(0xFFFFFFFFu, m.z, off));
        m.w = fmaxf(m.w, __shfl_xor_sync(0xFFFFFFFFu, m.w, off));
    }
    if (lane == 0) wred[warp] = m;
    __syncthreads();
    float4 M;
    {
        float4 r0 = wred[0];
        #pragma unroll
        for (int wi = 1; wi < 8; wi++) {
            float4 t = wred[wi];
            r0.x = fmaxf(r0.x, t.x); r0.y = fmaxf(r0.y, t.y);
            r0.z = fmaxf(r0.z, t.z); r0.w = fmaxf(r0.w, t.w);
        }
        M = r0;
    }
    __syncthreads();

    float4 sum = make_float4(0.f, 0.f, 0.f, 0.f);
    for (int i = tid; i < len; i += NT) {
        float4 s = g_scores[start + i];
        sum.x += __expf(s.x - M.x); sum.y += __expf(s.y - M.y);
        sum.z += __expf(s.z - M.z); sum.w += __expf(s.w - M.w);
    }
    #pragma unroll
    for (int off = 16; off > 0; off >>= 1) {
        sum.x += __shfl_xor_sync(0xFFFFFFFFu, sum.x, off);
        sum.y += __shfl_xor_sync(0xFFFFFFFFu, sum.y, off);
        sum.z += __shfl_xor_sync(0xFFFFFFFFu, sum.z, off);
        sum.w += __shfl_xor_sync(0xFFFFFFFFu, sum.w, off);
    }
    if (lane == 0) wred[warp] = sum;
    __syncthreads();
    float4 R;
    {
        float4 r0 = wred[0];
        #pragma unroll
        for (int wi = 1; wi < 8; wi++) {
            float4 t = wred[wi];
            r0.x += t.x; r0.y += t.y; r0.z += t.z; r0.w += t.w;
        }
        R.x = 1.0f / r0.x; R.y = 1.0f / r0.y;
        R.z = 1.0f / r0.z; R.w = 1.0f / r0.w;
    }

    float acc = 0.f;
    for (int c = 0; c < len; c += NT) {
        int cl = min(NT, len - c);
        __syncthreads();
        if (tid < cl) {
            float4 s = g_scores[start + c + tid];
            float a0 = __expf(s.x - M.x) * R.x;
            float a1 = __expf(s.y - M.y) * R.y;
            float a2 = __expf(s.z - M.z) * R.z;
            float a3 = __expf(s.w - M.w) * R.w;
            size_t p = (size_t)start + c + tid;
            out_attn[p]                 = a0;
            out_attn[(size_t)N + p]     = a1;
            out_attn[2 * (size_t)N + p] = a2;
            out_attn[3 * (size_t)N + p] = a3;
            w_s[tid] = 0.25f * (a0 + a1 + a2 + a3);
        }
        __syncthreads();
        for (int j = phase; j < cl; j += 2)
            acc += w_s[j] * x[(size_t)(start + c + j) * D + dd];
    }
    if (phase == 1) pred[dd] = acc;
    __syncthreads();
    if (phase == 0) out_pooled[(size_t)b * D + dd] = acc + pred[dd];
}

// ---------------------------------------------------------------------------
extern "C" void kernel_launch(void* const* d_in, const int* in_sizes, int n_in,
                              void* d_out, int out_size)
{
    const float* x    = (const float*)d_in[0];
    const void*  ids  = d_in[1];
    const float* W    = (const float*)d_in[2];
    const float* bias = (const float*)d_in[3];
    const float* temp = (const float*)d_in[4];

    int N = in_sizes[1];
    int B = (out_size - H * N) / D;
    if (B < 1) B = 1;
    if (B > BMAX) B = BMAX;

    float* out_pooled = (float*)d_out;                   // [B, D]
    float* out_attn   = (float*)d_out + (size_t)B * D;   // [H, N]

    const int SMEM = (ROWS_CAP * 128 + ROWS_CAP * 4 + 256 + 128 + 32) * 4;
    cudaFuncSetAttribute(k_fused, cudaFuncAttributeMaxDynamicSharedMemorySize, SMEM);

    k_bounds<<<(B + 256) / 256, 256>>>(ids, N, B);
    k_fused<<<B, NT, SMEM>>>(x, W, bias, temp, out_pooled, out_attn, N);
}

// round 5
// speedup vs baseline: 1.3713x; 1.0838x over previous
#include <cuda_runtime.h>
#include <math.h>

#define D 128
#define H 4
#define NMAX 500000
#define BMAX 8192
#define ROWS_CAP 256
#define NT 256          // threads per block (8 warps)

// Global scratch (fallback path only) + segment starts.
__device__ float4 g_scores[NMAX];
__device__ int    g_seg_start[BMAX + 1];

// ---------------------------------------------------------------------------
// Dtype-agnostic ids (reference claims int64 but JAX x64-off gives int32).
// ---------------------------------------------------------------------------
__device__ __forceinline__ bool ids_are_64bit(const int* ids32, int N) {
    int j = ((N - 1) & 1) ? (N - 1) : (N - 2);
    if (j < 0) j = 0;
    return ids32[j] == 0;   // high word of small int64 == 0; late int32 id != 0
}
__device__ __forceinline__ int get_id_raw(const void* ids, bool is64, int n) {
    return is64 ? (int)((const long long*)ids)[n] : ((const int*)ids)[n];
}

// ---------------------------------------------------------------------------
// Kernel 0: seg_start[b] = lower_bound(ids, b). One thread per boundary.
// ---------------------------------------------------------------------------
__global__ void k_bounds(const void* __restrict__ ids, int N, int B) {
    int b = blockIdx.x * blockDim.x + threadIdx.x;
    if (b > B) return;
    bool is64 = ids_are_64bit((const int*)ids, N);
    int lo = 0, hi = N;
    while (lo < hi) {
        int mid = (lo + hi) >> 1;
        if (get_id_raw(ids, is64, mid) < b) lo = mid + 1; else hi = mid;
    }
    g_seg_start[b] = lo;
}

// ---------------------------------------------------------------------------
// Fused kernel: one block (256 threads) per segment. NO smem x tile —
// x is read twice from global; the second (pooling) read hits L1 (segment
// ~31KB, L1 has its full 228KB carveout since smem use is ~9KB).
// Dynamic smem (floats):
//   sc_s  [ROWS_CAP*4]  per-node head scores (float4)    4KB
//   w_s   [ROWS_CAP]    per-node mean attention weight   1KB
//   pool4 [8*32*4]      pooling partials (float4/warp)   4KB
//   wred  [8*4]         warp-reduce scratch              128B
// ---------------------------------------------------------------------------
__global__ void __launch_bounds__(NT) k_fused(
    const float* __restrict__ x,
    const float* __restrict__ W,
    const float* __restrict__ bias,
    const float* __restrict__ temp,
    float* __restrict__ out_pooled,   // [B, D]
    float* __restrict__ out_attn,     // [H, N]
    int N)
{
    extern __shared__ float sdyn[];
    float4* sc_s  = (float4*)sdyn;                          // ROWS_CAP float4
    float*  w_s   = sdyn + ROWS_CAP * 4;                    // ROWS_CAP floats
    float4* pool4 = (float4*)(w_s + ROWS_CAP);              // 8*32 float4
    float4* wred  = pool4 + 8 * 32;                         // 8 float4

    int b     = blockIdx.x;
    int start = g_seg_start[b];
    int end   = g_seg_start[b + 1];
    int len   = end - start;
    int tid   = threadIdx.x;
    int lane  = tid & 31, warp = tid >> 5;

    // W rows per lane (L1/L2-hot, 2KB) + bias + 1/T
    float4 w0 = ((const float4*)W)[lane];
    float4 w1 = ((const float4*)W)[32 + lane];
    float4 w2 = ((const float4*)W)[64 + lane];
    float4 w3 = ((const float4*)W)[96 + lane];
    float4 bv = *(const float4*)bias;
    float  tinv = 1.0f / temp[0];

    const float4* xg4 = (const float4*)(x + (size_t)start * D);

    if (len <= ROWS_CAP) {
        // ---- scores: warp per node, x straight from global (coalesced) ----
        for (int n = warp; n < len; n += 8) {
            float4 xv = xg4[n * 32 + lane];
            float s0 = xv.x * w0.x + xv.y * w0.y + xv.z * w0.z + xv.w * w0.w;
            float s1 = xv.x * w1.x + xv.y * w1.y + xv.z * w1.z + xv.w * w1.w;
            float s2 = xv.x * w2.x + xv.y * w2.y + xv.z * w2.z + xv.w * w2.w;
            float s3 = xv.x * w3.x + xv.y * w3.y + xv.z * w3.z + xv.w * w3.w;
            #pragma unroll
            for (int off = 16; off > 0; off >>= 1) {
                s0 += __shfl_xor_sync(0xFFFFFFFFu, s0, off);
                s1 += __shfl_xor_sync(0xFFFFFFFFu, s1, off);
                s2 += __shfl_xor_sync(0xFFFFFFFFu, s2, off);
                s3 += __shfl_xor_sync(0xFFFFFFFFu, s3, off);
            }
            if (lane == 0) {
                float4 sc;
                sc.x = (s0 + bv.x) * tinv;
                sc.y = (s1 + bv.y) * tinv;
                sc.z = (s2 + bv.z) * tinv;
                sc.w = (s3 + bv.w) * tinv;
                sc_s[n] = sc;
            }
        }
        __syncthreads();

        // ---- softmax stats: thread owns <=1 node (len <= 256) ----
        float4 sv = (tid < len) ? sc_s[tid]
                                : make_float4(-INFINITY, -INFINITY, -INFINITY, -INFINITY);
        float4 m = sv;
        #pragma unroll
        for (int off = 16; off > 0; off >>= 1) {
            m.x = fmaxf(m.x, __shfl_xor_sync(0xFFFFFFFFu, m.x, off));
            m.y = fmaxf(m.y, __shfl_xor_sync(0xFFFFFFFFu, m.y, off));
            m.z = fmaxf(m.z, __shfl_xor_sync(0xFFFFFFFFu, m.z, off));
            m.w = fmaxf(m.w, __shfl_xor_sync(0xFFFFFFFFu, m.w, off));
        }
        if (lane == 0) wred[warp] = m;
        __syncthreads();
        float4 M;
        {
            float4 r0 = wred[0];
            #pragma unroll
            for (int wi = 1; wi < 8; wi++) {
                float4 t = wred[wi];
                r0.x = fmaxf(r0.x, t.x); r0.y = fmaxf(r0.y, t.y);
                r0.z = fmaxf(r0.z, t.z); r0.w = fmaxf(r0.w, t.w);
            }
            M = r0;
        }
        __syncthreads();

        float e0 = 0.f, e1 = 0.f, e2 = 0.f, e3 = 0.f;
        if (tid < len) {
            e0 = __expf(sv.x - M.x); e1 = __expf(sv.y - M.y);
            e2 = __expf(sv.z - M.z); e3 = __expf(sv.w - M.w);
        }
        float4 s4 = make_float4(e0, e1, e2, e3);
        #pragma unroll
        for (int off = 16; off > 0; off >>= 1) {
            s4.x += __shfl_xor_sync(0xFFFFFFFFu, s4.x, off);
            s4.y += __shfl_xor_sync(0xFFFFFFFFu, s4.y, off);
            s4.z += __shfl_xor_sync(0xFFFFFFFFu, s4.z, off);
            s4.w += __shfl_xor_sync(0xFFFFFFFFu, s4.w, off);
        }
        if (lane == 0) wred[warp] = s4;
        __syncthreads();
        float4 R;
        {
            float4 r0 = wred[0];
            #pragma unroll
            for (int wi = 1; wi < 8; wi++) {
                float4 t = wred[wi];
                r0.x += t.x; r0.y += t.y; r0.z += t.z; r0.w += t.w;
            }
            R.x = (len > 0) ? 1.0f / r0.x : 0.f;
            R.y = (len > 0) ? 1.0f / r0.y : 0.f;
            R.z = (len > 0) ? 1.0f / r0.z : 0.f;
            R.w = (len > 0) ? 1.0f / r0.w : 0.f;
        }

        // ---- attn output (coalesced per head) + per-node mean weight ----
        if (tid < len) {
            float a0 = e0 * R.x, a1 = e1 * R.y, a2 = e2 * R.z, a3 = e3 * R.w;
            size_t p = (size_t)start + tid;
            out_attn[p]                 = a0;
            out_attn[(size_t)N + p]     = a1;
            out_attn[2 * (size_t)N + p] = a2;
            out_attn[3 * (size_t)N + p] = a3;
            w_s[tid] = 0.25f * (a0 + a1 + a2 + a3);
        }
        __syncthreads();

        // ---- pooled: warp = row-phase (8-way), lane = float4 column ----
        // x re-read from global; hits L1 (just streamed, fits in carveout).
        float4 acc = make_float4(0.f, 0.f, 0.f, 0.f);
        for (int j = warp; j < len; j += 8) {
            float wj = w_s[j];
            float4 v = xg4[j * 32 + lane];
            acc.x += wj * v.x; acc.y += wj * v.y;
            acc.z += wj * v.z; acc.w += wj * v.w;
        }
        pool4[warp * 32 + lane] = acc;
        __syncthreads();
        if (warp == 0) {
            float4 r = pool4[lane];
            #pragma unroll
            for (int p = 1; p < 8; p++) {
                float4 t = pool4[p * 32 + lane];
                r.x += t.x; r.y += t.y; r.z += t.z; r.w += t.w;
            }
            ((float4*)(out_pooled + (size_t)b * D))[lane] = r;
        }
        return;
    }

    // ======================= fallback (len > ROWS_CAP) =======================
    for (int n = warp; n < len; n += 8) {
        float4 xv = xg4[n * 32 + lane];
        float s0 = xv.x * w0.x + xv.y * w0.y + xv.z * w0.z + xv.w * w0.w;
        float s1 = xv.x * w1.x + xv.y * w1.y + xv.z * w1.z + xv.w * w1.w;
        float s2 = xv.x * w2.x + xv.y * w2.y + xv.z * w2.z + xv.w * w2.w;
        float s3 = xv.x * w3.x + xv.y * w3.y + xv.z * w3.z + xv.w * w3.w;
        #pragma unroll
        for (int off = 16; off > 0; off >>= 1) {
            s0 += __shfl_xor_sync(0xFFFFFFFFu, s0, off);
            s1 += __shfl_xor_sync(0xFFFFFFFFu, s1, off);
            s2 += __shfl_xor_sync(0xFFFFFFFFu, s2, off);
            s3 += __shfl_xor_sync(0xFFFFFFFFu, s3, off);
        }
        if (lane == 0) {
            float4 sc;
            sc.x = (s0 + bv.x) * tinv; sc.y = (s1 + bv.y) * tinv;
            sc.z = (s2 + bv.z) * tinv; sc.w = (s3 + bv.w) * tinv;
            g_scores[start + n] = sc;
        }
    }
    __syncthreads();

    float4 m = make_float4(-INFINITY, -INFINITY, -INFINITY, -INFINITY);
    for (int i = tid; i < len; i += NT) {
        float4 s = g_scores[start + i];
        m.x = fmaxf(m.x, s.x); m.y = fmaxf(m.y, s.y);
        m.z = fmaxf(m.z, s.z); m.w = fmaxf(m.w, s.w);
    }
    #pragma unroll
    for (int off = 16; off > 0; off >>= 1) {
        m.x = fmaxf(m.x, __shfl_xor_sync(0xFFFFFFFFu, m.x, off));
        m.y = fmaxf(m.y, __shfl_xor_sync(0xFFFFFFFFu, m.y, off));
        m.z = fmaxf(m.z, __shfl_xor_sync(0xFFFFFFFFu, m.z, off));
        m.w = fmaxf(m.w, __shfl_xor_sync(0xFFFFFFFFu, m.w, off));
    }
    if (lane == 0) wred[warp] = m;
    __syncthreads();
    float4 M;
    {
        float4 r0 = wred[0];
        #pragma unroll
        for (int wi = 1; wi < 8; wi++) {
            float4 t = wred[wi];
            r0.x = fmaxf(r0.x, t.x); r0.y = fmaxf(r0.y, t.y);
            r0.z = fmaxf(r0.z, t.z); r0.w = fmaxf(r0.w, t.w);
        }
        M = r0;
    }
    __syncthreads();

    float4 sum = make_float4(0.f, 0.f, 0.f, 0.f);
    for (int i = tid; i < len; i += NT) {
        float4 s = g_scores[start + i];
        sum.x += __expf(s.x - M.x); sum.y += __expf(s.y - M.y);
        sum.z += __expf(s.z - M.z); sum.w += __expf(s.w - M.w);
    }
    #pragma unroll
    for (int off = 16; off > 0; off >>= 1) {
        sum.x += __shfl_xor_sync(0xFFFFFFFFu, sum.x, off);
        sum.y += __shfl_xor_sync(0xFFFFFFFFu, sum.y, off);
        sum.z += __shfl_xor_sync(0xFFFFFFFFu, sum.z, off);
        sum.w += __shfl_xor_sync(0xFFFFFFFFu, sum.w, off);
    }
    if (lane == 0) wred[warp] = sum;
    __syncthreads();
    float4 R;
    {
        float4 r0 = wred[0];
        #pragma unroll
        for (int wi = 1; wi < 8; wi++) {
            float4 t = wred[wi];
            r0.x += t.x; r0.y += t.y; r0.z += t.z; r0.w += t.w;
        }
        R.x = 1.0f / r0.x; R.y = 1.0f / r0.y;
        R.z = 1.0f / r0.z; R.w = 1.0f / r0.w;
    }

    float4 acc = make_float4(0.f, 0.f, 0.f, 0.f);
    for (int c = 0; c < len; c += ROWS_CAP) {
        int cl = min(ROWS_CAP, len - c);
        __syncthreads();
        if (tid < cl) {
            float4 s = g_scores[start + c + tid];
            float a0 = __expf(s.x - M.x) * R.x;
            float a1 = __expf(s.y - M.y) * R.y;
            float a2 = __expf(s.z - M.z) * R.z;
            float a3 = __expf(s.w - M.w) * R.w;
            size_t p = (size_t)start + c + tid;
            out_attn[p]                 = a0;
            out_attn[(size_t)N + p]     = a1;
            out_attn[2 * (size_t)N + p] = a2;
            out_attn[3 * (size_t)N + p] = a3;
            w_s[tid] = 0.25f * (a0 + a1 + a2 + a3);
        }
        __syncthreads();
        for (int j = warp; j < cl; j += 8) {
            float wj = w_s[j];
            float4 v = xg4[(c + j) * 32 + lane];
            acc.x += wj * v.x; acc.y += wj * v.y;
            acc.z += wj * v.z; acc.w += wj * v.w;
        }
    }
    __syncthreads();
    pool4[warp * 32 + lane] = acc;
    __syncthreads();
    if (warp == 0) {
        float4 r = pool4[lane];
        #pragma unroll
        for (int p = 1; p < 8; p++) {
            float4 t = pool4[p * 32 + lane];
            r.x += t.x; r.y += t.y; r.z += t.z; r.w += t.w;
        }
        ((float4*)(out_pooled + (size_t)b * D))[lane] = r;
    }
}

// ---------------------------------------------------------------------------
extern "C" void kernel_launch(void* const* d_in, const int* in_sizes, int n_in,
                              void* d_out, int out_size)
{
    const float* x    = (const float*)d_in[0];
    const void*  ids  = d_in[1];
    const float* W    = (const float*)d_in[2];
    const float* bias = (const float*)d_in[3];
    const float* temp = (const float*)d_in[4];

    int N = in_sizes[1];
    int B = (out_size - H * N) / D;
    if (B < 1) B = 1;
    if (B > BMAX) B = BMAX;

    float* out_pooled = (float*)d_out;                   // [B, D]
    float* out_attn   = (float*)d_out + (size_t)B * D;   // [H, N]

    const int SMEM = (ROWS_CAP * 4 + ROWS_CAP + 8 * 32 * 4 + 8 * 4) * 4;

    k_bounds<<<(B + 256) / 256, 256>>>(ids, N, B);
    k_fused<<<B, NT, SMEM>>>(x, W, bias, temp, out_pooled, out_attn, N);
}

// round 7
// speedup vs baseline: 1.4443x; 1.0532x over previous
#include <cuda_runtime.h>
#include <math.h>

#define D 128
#define H 4
#define NMAX 500000
#define BMAX 8192
#define ROWS_CAP 256
#define NT 256          // 8 warps
#define KREG 8          // register-resident rows per warp (covers len <= 64)

// Global scratch (fallback path only) + segment starts.
__device__ float4 g_scores[NMAX];
__device__ int    g_seg_start[BMAX + 1];

// ---------------------------------------------------------------------------
// Dtype-agnostic ids (reference claims int64 but JAX x64-off gives int32).
// ---------------------------------------------------------------------------
__device__ __forceinline__ bool ids_are_64bit(const int* ids32, int N) {
    int j = ((N - 1) & 1) ? (N - 1) : (N - 2);
    if (j < 0) j = 0;
    return ids32[j] == 0;
}
__device__ __forceinline__ int get_id_raw(const void* ids, bool is64, int n) {
    return is64 ? (int)((const long long*)ids)[n] : ((const int*)ids)[n];
}

// ---------------------------------------------------------------------------
// Kernel 0: seg_start[b] = lower_bound(ids, b).
// ---------------------------------------------------------------------------
__global__ void k_bounds(const void* __restrict__ ids, int N, int B) {
    int b = blockIdx.x * blockDim.x + threadIdx.x;
    if (b > B) return;
    bool is64 = ids_are_64bit((const int*)ids, N);
    int lo = 0, hi = N;
    while (lo < hi) {
        int mid = (lo + hi) >> 1;
        if (get_id_raw(ids, is64, mid) < b) lo = mid + 1; else hi = mid;
    }
    g_seg_start[b] = lo;
}

// ---------------------------------------------------------------------------
// Fused kernel: one block (256 thr) per segment.
//  - warp w owns rows {w, w+8, w+16, ...}; first KREG of them are prefetched
//    into registers with 8-deep MLP and reused for pooling (zero extra loads).
//  - rows >= 64 take an L1-hit re-read in the pooling phase.
// smem: sc_s[ROWS_CAP]f4 | w_s[ROWS_CAP]f | pool4[8*32]f4 | wred[8]f4
// ---------------------------------------------------------------------------
__global__ void __launch_bounds__(NT, 3) k_fused(
    const float* __restrict__ x,
    const float* __restrict__ W,
    const float* __restrict__ bias,
    const float* __restrict__ temp,
    float* __restrict__ out_pooled,   // [B, D]
    float* __restrict__ out_attn,     // [H, N]
    int N)
{
    extern __shared__ float sdyn[];
    float4* sc_s  = (float4*)sdyn;
    float*  w_s   = sdyn + ROWS_CAP * 4;
    float4* pool4 = (float4*)(w_s + ROWS_CAP);
    float4* wred  = pool4 + 8 * 32;

    int b     = blockIdx.x;
    int start = g_seg_start[b];
    int end   = g_seg_start[b + 1];
    int len   = end - start;
    int tid   = threadIdx.x;
    int lane  = tid & 31, warp = tid >> 5;

    float4 w0 = ((const float4*)W)[lane];
    float4 w1 = ((const float4*)W)[32 + lane];
    float4 w2 = ((const float4*)W)[64 + lane];
    float4 w3 = ((const float4*)W)[96 + lane];
    float4 bv = *(const float4*)bias;
    float  tinv = 1.0f / temp[0];

    const float4* xg4 = (const float4*)(x + (size_t)start * D);

    if (len <= ROWS_CAP) {
        // ---- prefetch: 8 independent row loads per warp (MLP=8) ----
        float4 xr[KREG];
        #pragma unroll
        for (int k = 0; k < KREG; k++) {
            int n = warp + k * 8;
            if (n < len) xr[k] = xg4[n * 32 + lane];
        }

        // ---- scores from registers ----
        #pragma unroll
        for (int k = 0; k < KREG; k++) {
            int n = warp + k * 8;
            if (n < len) {
                float4 xv = xr[k];
                float s0 = xv.x * w0.x + xv.y * w0.y + xv.z * w0.z + xv.w * w0.w;
                float s1 = xv.x * w1.x + xv.y * w1.y + xv.z * w1.z + xv.w * w1.w;
                float s2 = xv.x * w2.x + xv.y * w2.y + xv.z * w2.z + xv.w * w2.w;
                float s3 = xv.x * w3.x + xv.y * w3.y + xv.z * w3.z + xv.w * w3.w;
                #pragma unroll
                for (int off = 16; off > 0; off >>= 1) {
                    s0 += __shfl_xor_sync(0xFFFFFFFFu, s0, off);
                    s1 += __shfl_xor_sync(0xFFFFFFFFu, s1, off);
                    s2 += __shfl_xor_sync(0xFFFFFFFFu, s2, off);
                    s3 += __shfl_xor_sync(0xFFFFFFFFu, s3, off);
                }
                if (lane == 0) {
                    float4 sc;
                    sc.x = (s0 + bv.x) * tinv;
                    sc.y = (s1 + bv.y) * tinv;
                    sc.z = (s2 + bv.z) * tinv;
                    sc.w = (s3 + bv.w) * tinv;
                    sc_s[n] = sc;
                }
            }
        }
        // ---- tail rows (len > 64): load + score directly ----
        for (int n = warp + KREG * 8; n < len; n += 8) {
            float4 xv = xg4[n * 32 + lane];
            float s0 = xv.x * w0.x + xv.y * w0.y + xv.z * w0.z + xv.w * w0.w;
            float s1 = xv.x * w1.x + xv.y * w1.y + xv.z * w1.z + xv.w * w1.w;
            float s2 = xv.x * w2.x + xv.y * w2.y + xv.z * w2.z + xv.w * w2.w;
            float s3 = xv.x * w3.x + xv.y * w3.y + xv.z * w3.z + xv.w * w3.w;
            #pragma unroll
            for (int off = 16; off > 0; off >>= 1) {
                s0 += __shfl_xor_sync(0xFFFFFFFFu, s0, off);
                s1 += __shfl_xor_sync(0xFFFFFFFFu, s1, off);
                s2 += __shfl_xor_sync(0xFFFFFFFFu, s2, off);
                s3 += __shfl_xor_sync(0xFFFFFFFFu, s3, off);
            }
            if (lane == 0) {
                float4 sc;
                sc.x = (s0 + bv.x) * tinv; sc.y = (s1 + bv.y) * tinv;
                sc.z = (s2 + bv.z) * tinv; sc.w = (s3 + bv.w) * tinv;
                sc_s[n] = sc;
            }
        }
        __syncthreads();

        // ---- softmax stats: thread owns <=1 node ----
        float4 sv = (tid < len) ? sc_s[tid]
                                : make_float4(-INFINITY, -INFINITY, -INFINITY, -INFINITY);
        float4 m = sv;
        #pragma unroll
        for (int off = 16; off > 0; off >>= 1) {
            m.x = fmaxf(m.x, __shfl_xor_sync(0xFFFFFFFFu, m.x, off));
            m.y = fmaxf(m.y, __shfl_xor_sync(0xFFFFFFFFu, m.y, off));
            m.z = fmaxf(m.z, __shfl_xor_sync(0xFFFFFFFFu, m.z, off));
            m.w = fmaxf(m.w, __shfl_xor_sync(0xFFFFFFFFu, m.w, off));
        }
        if (lane == 0) wred[warp] = m;
        __syncthreads();
        float4 M;
        {
            float4 r0 = wred[0];
            #pragma unroll
            for (int wi = 1; wi < 8; wi++) {
                float4 t = wred[wi];
                r0.x = fmaxf(r0.x, t.x); r0.y = fmaxf(r0.y, t.y);
                r0.z = fmaxf(r0.z, t.z); r0.w = fmaxf(r0.w, t.w);
            }
            M = r0;
        }
        __syncthreads();

        float e0 = 0.f, e1 = 0.f, e2 = 0.f, e3 = 0.f;
        if (tid < len) {
            e0 = __expf(sv.x - M.x); e1 = __expf(sv.y - M.y);
            e2 = __expf(sv.z - M.z); e3 = __expf(sv.w - M.w);
        }
        float4 s4 = make_float4(e0, e1, e2, e3);
        #pragma unroll
        for (int off = 16; off > 0; off >>= 1) {
            s4.x += __shfl_xor_sync(0xFFFFFFFFu, s4.x, off);
            s4.y += __shfl_xor_sync(0xFFFFFFFFu, s4.y, off);
            s4.z += __shfl_xor_sync(0xFFFFFFFFu, s4.z, off);
            s4.w += __shfl_xor_sync(0xFFFFFFFFu, s4.w, off);
        }
        if (lane == 0) wred[warp] = s4;
        __syncthreads();
        float4 R;
        {
            float4 r0 = wred[0];
            #pragma unroll
            for (int wi = 1; wi < 8; wi++) {
                float4 t = wred[wi];
                r0.x += t.x; r0.y += t.y; r0.z += t.z; r0.w += t.w;
            }
            R.x = (len > 0) ? 1.0f / r0.x : 0.f;
            R.y = (len > 0) ? 1.0f / r0.y : 0.f;
            R.z = (len > 0) ? 1.0f / r0.z : 0.f;
            R.w = (len > 0) ? 1.0f / r0.w : 0.f;
        }

        // ---- attn output + per-node mean weight ----
        if (tid < len) {
            float a0 = e0 * R.x, a1 = e1 * R.y, a2 = e2 * R.z, a3 = e3 * R.w;
            size_t p = (size_t)start + tid;
            out_attn[p]                 = a0;
            out_attn[(size_t)N + p]     = a1;
            out_attn[2 * (size_t)N + p] = a2;
            out_attn[3 * (size_t)N + p] = a3;
            w_s[tid] = 0.25f * (a0 + a1 + a2 + a3);
        }
        __syncthreads();

        // ---- pooled: register-resident rows need NO loads ----
        float4 acc = make_float4(0.f, 0.f, 0.f, 0.f);
        #pragma unroll
        for (int k = 0; k < KREG; k++) {
            int n = warp + k * 8;
            if (n < len) {
                float wj = w_s[n];
                acc.x += wj * xr[k].x; acc.y += wj * xr[k].y;
                acc.z += wj * xr[k].z; acc.w += wj * xr[k].w;
            }
        }
        for (int n = warp + KREG * 8; n < len; n += 8) {   // L1-hit re-read
            float wj = w_s[n];
            float4 v = xg4[n * 32 + lane];
            acc.x += wj * v.x; acc.y += wj * v.y;
            acc.z += wj * v.z; acc.w += wj * v.w;
        }
        pool4[warp * 32 + lane] = acc;
        __syncthreads();
        if (warp == 0) {
            float4 r = pool4[lane];
            #pragma unroll
            for (int p = 1; p < 8; p++) {
                float4 t = pool4[p * 32 + lane];
                r.x += t.x; r.y += t.y; r.z += t.z; r.w += t.w;
            }
            ((float4*)(out_pooled + (size_t)b * D))[lane] = r;
        }
        return;
    }

    // ======================= fallback (len > ROWS_CAP) =======================
    for (int n = warp; n < len; n += 8) {
        float4 xv = xg4[n * 32 + lane];
        float s0 = xv.x * w0.x + xv.y * w0.y + xv.z * w0.z + xv.w * w0.w;
        float s1 = xv.x * w1.x + xv.y * w1.y + xv.z * w1.z + xv.w * w1.w;
        float s2 = xv.x * w2.x + xv.y * w2.y + xv.z * w2.z + xv.w * w2.w;
        float s3 = xv.x * w3.x + xv.y * w3.y + xv.z * w3.z + xv.w * w3.w;
        #pragma unroll
        for (int off = 16; off > 0; off >>= 1) {
            s0 += __shfl_xor_sync(0xFFFFFFFFu, s0, off);
            s1 += __shfl_xor_sync(0xFFFFFFFFu, s1, off);
            s2 += __shfl_xor_sync(0xFFFFFFFFu, s2, off);
            s3 += __shfl_xor_sync(0xFFFFFFFFu, s3, off);
        }
        if (lane == 0) {
            float4 sc;
            sc.x = (s0 + bv.x) * tinv; sc.y = (s1 + bv.y) * tinv;
            sc.z = (s2 + bv.z) * tinv; sc.w = (s3 + bv.w) * tinv;
            g_scores[start + n] = sc;
        }
    }
    __syncthreads();

    float4 m = make_float4(-INFINITY, -INFINITY, -INFINITY, -INFINITY);
    for (int i = tid; i < len; i += NT) {
        float4 s = g_scores[start + i];
        m.x = fmaxf(m.x, s.x); m.y = fmaxf(m.y, s.y);
        m.z = fmaxf(m.z, s.z); m.w = fmaxf(m.w, s.w);
    }
    #pragma unroll
    for (int off = 16; off > 0; off >>= 1) {
        m.x = fmaxf(m.x, __shfl_xor_sync(0xFFFFFFFFu, m.x, off));
        m.y = fmaxf(m.y, __shfl_xor_sync(0xFFFFFFFFu, m.y, off));
        m.z = fmaxf(m.z, __shfl_xor_sync(0xFFFFFFFFu, m.z, off));
        m.w = fmaxf(m.w, __shfl_xor_sync(0xFFFFFFFFu, m.w, off));
    }
    if (lane == 0) wred[warp] = m;
    __syncthreads();
    float4 M;
    {
        float4 r0 = wred[0];
        #pragma unroll
        for (int wi = 1; wi < 8; wi++) {
            float4 t = wred[wi];
            r0.x = fmaxf(r0.x, t.x); r0.y = fmaxf(r0.y, t.y);
            r0.z = fmaxf(r0.z, t.z); r0.w = fmaxf(r0.w, t.w);
        }
        M = r0;
    }
    __syncthreads();

    float4 sum = make_float4(0.f, 0.f, 0.f, 0.f);
    for (int i = tid; i < len; i += NT) {
        float4 s = g_scores[start + i];
        sum.x += __expf(s.x - M.x); sum.y += __expf(s.y - M.y);
        sum.z += __expf(s.z - M.z); sum.w += __expf(s.w - M.w);
    }
    #pragma unroll
    for (int off = 16; off > 0; off >>= 1) {
        sum.x += __shfl_xor_sync(0xFFFFFFFFu, sum.x, off);
        sum.y += __shfl_xor_sync(0xFFFFFFFFu, sum.y, off);
        sum.z += __shfl_xor_sync(0xFFFFFFFFu, sum.z, off);
        sum.w += __shfl_xor_sync(0xFFFFFFFFu, sum.w, off);
    }
    if (lane == 0) wred[warp] = sum;
    __syncthreads();
    float4 R;
    {
        float4 r0 = wred[0];
        #pragma unroll
        for (int wi = 1; wi < 8; wi++) {
            float4 t = wred[wi];
            r0.x += t.x; r0.y += t.y; r0.z += t.z; r0.w += t.w;
        }
        R.x = 1.0f / r0.x; R.y = 1.0f / r0.y;
        R.z = 1.0f / r0.z; R.w = 1.0f / r0.w;
    }

    float4 acc = make_float4(0.f, 0.f, 0.f, 0.f);
    for (int c = 0; c < len; c += ROWS_CAP) {
        int cl = min(ROWS_CAP, len - c);
        __syncthreads();
        if (tid < cl) {
            float4 s = g_scores[start + c + tid];
            float a0 = __expf(s.x - M.x) * R.x;
            float a1 = __expf(s.y - M.y) * R.y;
            float a2 = __expf(s.z - M.z) * R.z;
            float a3 = __expf(s.w - M.w) * R.w;
            size_t p = (size_t)start + c + tid;
            out_attn[p]                 = a0;
            out_attn[(size_t)N + p]     = a1;
            out_attn[2 * (size_t)N + p] = a2;
            out_attn[3 * (size_t)N + p] = a3;
            w_s[tid] = 0.25f * (a0 + a1 + a2 + a3);
        }
        __syncthreads();
        for (int j = warp; j < cl; j += 8) {
            float wj = w_s[j];
            float4 v = xg4[(c + j) * 32 + lane];
            acc.x += wj * v.x; acc.y += wj * v.y;
            acc.z += wj * v.z; acc.w += wj * v.w;
        }
    }
    __syncthreads();
    pool4[warp * 32 + lane] = acc;
    __syncthreads();
    if (warp == 0) {
        float4 r = pool4[lane];
        #pragma unroll
        for (int p = 1; p < 8; p++) {
            float4 t = pool4[p * 32 + lane];
            r.x += t.x; r.y += t.y; r.z += t.z; r.w += t.w;
        }
        ((float4*)(out_pooled + (size_t)b * D))[lane] = r;
    }
}

// ---------------------------------------------------------------------------
extern "C" void kernel_launch(void* const* d_in, const int* in_sizes, int n_in,
                              void* d_out, int out_size)
{
    const float* x    = (const float*)d_in[0];
    const void*  ids  = d_in[1];
    const float* W    = (const float*)d_in[2];
    const float* bias = (const float*)d_in[3];
    const float* temp = (const float*)d_in[4];

    int N = in_sizes[1];
    int B = (out_size - H * N) / D;
    if (B < 1) B = 1;
    if (B > BMAX) B = BMAX;

    float* out_pooled = (float*)d_out;                   // [B, D]
    float* out_attn   = (float*)d_out + (size_t)B * D;   // [H, N]

    const int SMEM = (ROWS_CAP * 4 + ROWS_CAP + 8 * 32 * 4 + 8 * 4) * 4;

    k_bounds<<<(B + 256) / 256, 256>>>(ids, N, B);
    k_fused<<<B, NT, SMEM>>>(x, W, bias, temp, out_pooled, out_attn, N);
}

// round 8
// speedup vs baseline: 1.6873x; 1.1682x over previous
#include <cuda_runtime.h>
#include <math.h>

#define D 128
#define H 4
#define NMAX 500000
#define BMAX 8192
#define ROWS_CAP 256
#define NT 256          // 8 warps
#define KREG 8          // register-resident rows per warp (covers len <= 64)

// Global scratch (fallback path only) + segment starts.
__device__ float4 g_scores[NMAX];
__device__ int    g_seg_start[BMAX + 1];

// ---------------------------------------------------------------------------
// Dtype-agnostic ids (reference claims int64 but JAX x64-off gives int32).
// ---------------------------------------------------------------------------
__device__ __forceinline__ bool ids_are_64bit(const int* ids32, int N) {
    int j = ((N - 1) & 1) ? (N - 1) : (N - 2);
    if (j < 0) j = 0;
    return ids32[j] == 0;
}
__device__ __forceinline__ int get_id_raw(const void* ids, bool is64, int n) {
    return is64 ? (int)((const long long*)ids)[n] : ((const int*)ids)[n];
}

// ---------------------------------------------------------------------------
// Kernel 0: seg_start[b] = lower_bound(ids, b).
// ---------------------------------------------------------------------------
__global__ void k_bounds(const void* __restrict__ ids, int N, int B) {
    int b = blockIdx.x * blockDim.x + threadIdx.x;
    if (b > B) return;
    bool is64 = ids_are_64bit((const int*)ids, N);
    int lo = 0, hi = N;
    while (lo < hi) {
        int mid = (lo + hi) >> 1;
        if (get_id_raw(ids, is64, mid) < b) lo = mid + 1; else hi = mid;
    }
    g_seg_start[b] = lo;
}

// ---------------------------------------------------------------------------
// 4-head warp reduction in 6 shuffles (vs 20): merge heads pairwise with
// select+xor, then butterfly. Returns: lane l holds full 32-lane sum of
// head (l & 3).
// ---------------------------------------------------------------------------
__device__ __forceinline__ float reduce4_heads(float s0, float s1, float s2,
                                               float s3, int lane) {
    const unsigned FULL = 0xFFFFFFFFu;
    float a01_send = (lane & 1) ? s0 : s1;
    float a01 = ((lane & 1) ? s1 : s0) + __shfl_xor_sync(FULL, a01_send, 1);
    float a23_send = (lane & 1) ? s2 : s3;
    float a23 = ((lane & 1) ? s3 : s2) + __shfl_xor_sync(FULL, a23_send, 1);
    float b_send = (lane & 2) ? a01 : a23;
    float v = ((lane & 2) ? a23 : a01) + __shfl_xor_sync(FULL, b_send, 2);
    v += __shfl_xor_sync(FULL, v, 4);
    v += __shfl_xor_sync(FULL, v, 8);
    v += __shfl_xor_sync(FULL, v, 16);
    return v;   // head (lane & 3), replicated across each 4-lane group
}

// ---------------------------------------------------------------------------
// Fused kernel: one block (256 thr) per segment.
// smem: sc_s[ROWS_CAP]f4 | w_s[ROWS_CAP]f | pool4[8*32]f4 | wred[8]f4
// ---------------------------------------------------------------------------
__global__ void __launch_bounds__(NT, 3) k_fused(
    const float* __restrict__ x,
    const float* __restrict__ W,
    const float* __restrict__ bias,
    const float* __restrict__ temp,
    float* __restrict__ out_pooled,   // [B, D]
    float* __restrict__ out_attn,     // [H, N]
    int N)
{
    extern __shared__ float sdyn[];
    float4* sc_s  = (float4*)sdyn;
    float*  sc_f  = sdyn;                      // scalar view of sc_s
    float*  w_s   = sdyn + ROWS_CAP * 4;
    float4* pool4 = (float4*)(w_s + ROWS_CAP);
    float4* wred  = pool4 + 8 * 32;

    int b     = blockIdx.x;
    int start = g_seg_start[b];
    int end   = g_seg_start[b + 1];
    int len   = end - start;
    int tid   = threadIdx.x;
    int lane  = tid & 31, warp = tid >> 5;

    float4 w0 = ((const float4*)W)[lane];
    float4 w1 = ((const float4*)W)[32 + lane];
    float4 w2 = ((const float4*)W)[64 + lane];
    float4 w3 = ((const float4*)W)[96 + lane];
    float  b_l  = bias[lane & 3];           // per-lane head bias
    float  tinv = 1.0f / temp[0];

    const float4* xg4 = (const float4*)(x + (size_t)start * D);

    if (len <= ROWS_CAP) {
        // ---- prefetch: 8 independent row loads per warp (MLP=8) ----
        float4 xr[KREG];
        #pragma unroll
        for (int k = 0; k < KREG; k++) {
            int n = warp + k * 8;
            if (n < len) xr[k] = xg4[n * 32 + lane];
        }

        // ---- scores from registers: 6-shuffle 4-head reduction ----
        #pragma unroll
        for (int k = 0; k < KREG; k++) {
            int n = warp + k * 8;
            if (n < len) {
                float4 xv = xr[k];
                float s0 = xv.x * w0.x + xv.y * w0.y + xv.z * w0.z + xv.w * w0.w;
                float s1 = xv.x * w1.x + xv.y * w1.y + xv.z * w1.z + xv.w * w1.w;
                float s2 = xv.x * w2.x + xv.y * w2.y + xv.z * w2.z + xv.w * w2.w;
                float s3 = xv.x * w3.x + xv.y * w3.y + xv.z * w3.z + xv.w * w3.w;
                float v = reduce4_heads(s0, s1, s2, s3, lane);
                if (lane < 4) sc_f[n * 4 + lane] = (v + b_l) * tinv;
            }
        }
        // ---- tail rows (len > 64) ----
        for (int n = warp + KREG * 8; n < len; n += 8) {
            float4 xv = xg4[n * 32 + lane];
            float s0 = xv.x * w0.x + xv.y * w0.y + xv.z * w0.z + xv.w * w0.w;
            float s1 = xv.x * w1.x + xv.y * w1.y + xv.z * w1.z + xv.w * w1.w;
            float s2 = xv.x * w2.x + xv.y * w2.y + xv.z * w2.z + xv.w * w2.w;
            float s3 = xv.x * w3.x + xv.y * w3.y + xv.z * w3.z + xv.w * w3.w;
            float v = reduce4_heads(s0, s1, s2, s3, lane);
            if (lane < 4) sc_f[n * 4 + lane] = (v + b_l) * tinv;
        }
        __syncthreads();

        // ---- softmax stats: thread owns <=1 node ----
        float4 sv = (tid < len) ? sc_s[tid]
                                : make_float4(-INFINITY, -INFINITY, -INFINITY, -INFINITY);
        float4 m = sv;
        #pragma unroll
        for (int off = 16; off > 0; off >>= 1) {
            m.x = fmaxf(m.x, __shfl_xor_sync(0xFFFFFFFFu, m.x, off));
            m.y = fmaxf(m.y, __shfl_xor_sync(0xFFFFFFFFu, m.y, off));
            m.z = fmaxf(m.z, __shfl_xor_sync(0xFFFFFFFFu, m.z, off));
            m.w = fmaxf(m.w, __shfl_xor_sync(0xFFFFFFFFu, m.w, off));
        }
        if (lane == 0) wred[warp] = m;
        __syncthreads();
        float4 M;
        {
            float4 r0 = wred[0];
            #pragma unroll
            for (int wi = 1; wi < 8; wi++) {
                float4 t = wred[wi];
                r0.x = fmaxf(r0.x, t.x); r0.y = fmaxf(r0.y, t.y);
                r0.z = fmaxf(r0.z, t.z); r0.w = fmaxf(r0.w, t.w);
            }
            M = r0;
        }
        __syncthreads();

        float e0 = 0.f, e1 = 0.f, e2 = 0.f, e3 = 0.f;
        if (tid < len) {
            e0 = __expf(sv.x - M.x); e1 = __expf(sv.y - M.y);
            e2 = __expf(sv.z - M.z); e3 = __expf(sv.w - M.w);
        }
        float4 s4 = make_float4(e0, e1, e2, e3);
        #pragma unroll
        for (int off = 16; off > 0; off >>= 1) {
            s4.x += __shfl_xor_sync(0xFFFFFFFFu, s4.x, off);
            s4.y += __shfl_xor_sync(0xFFFFFFFFu, s4.y, off);
            s4.z += __shfl_xor_sync(0xFFFFFFFFu, s4.z, off);
            s4.w += __shfl_xor_sync(0xFFFFFFFFu, s4.w, off);
        }
        if (lane == 0) wred[warp] = s4;
        __syncthreads();
        float4 R;
        {
            float4 r0 = wred[0];
            #pragma unroll
            for (int wi = 1; wi < 8; wi++) {
                float4 t = wred[wi];
                r0.x += t.x; r0.y += t.y; r0.z += t.z; r0.w += t.w;
            }
            R.x = (len > 0) ? 1.0f / r0.x : 0.f;
            R.y = (len > 0) ? 1.0f / r0.y : 0.f;
            R.z = (len > 0) ? 1.0f / r0.z : 0.f;
            R.w = (len > 0) ? 1.0f / r0.w : 0.f;
        }

        // ---- attn output + per-node mean weight ----
        if (tid < len) {
            float a0 = e0 * R.x, a1 = e1 * R.y, a2 = e2 * R.z, a3 = e3 * R.w;
            size_t p = (size_t)start + tid;
            out_attn[p]                 = a0;
            out_attn[(size_t)N + p]     = a1;
            out_attn[2 * (size_t)N + p] = a2;
            out_attn[3 * (size_t)N + p] = a3;
            w_s[tid] = 0.25f * (a0 + a1 + a2 + a3);
        }
        __syncthreads();

        // ---- pooled: register-resident rows need NO loads ----
        float4 acc = make_float4(0.f, 0.f, 0.f, 0.f);
        #pragma unroll
        for (int k = 0; k < KREG; k++) {
            int n = warp + k * 8;
            if (n < len) {
                float wj = w_s[n];
                acc.x += wj * xr[k].x; acc.y += wj * xr[k].y;
                acc.z += wj * xr[k].z; acc.w += wj * xr[k].w;
            }
        }
        for (int n = warp + KREG * 8; n < len; n += 8) {   // L1-hit re-read
            float wj = w_s[n];
            float4 v = xg4[n * 32 + lane];
            acc.x += wj * v.x; acc.y += wj * v.y;
            acc.z += wj * v.z; acc.w += wj * v.w;
        }
        pool4[warp * 32 + lane] = acc;
        __syncthreads();
        if (warp == 0) {
            float4 r = pool4[lane];
            #pragma unroll
            for (int p = 1; p < 8; p++) {
                float4 t = pool4[p * 32 + lane];
                r.x += t.x; r.y += t.y; r.z += t.z; r.w += t.w;
            }
            ((float4*)(out_pooled + (size_t)b * D))[lane] = r;
        }
        return;
    }

    // ======================= fallback (len > ROWS_CAP) =======================
    for (int n = warp; n < len; n += 8) {
        float4 xv = xg4[n * 32 + lane];
        float s0 = xv.x * w0.x + xv.y * w0.y + xv.z * w0.z + xv.w * w0.w;
        float s1 = xv.x * w1.x + xv.y * w1.y + xv.z * w1.z + xv.w * w1.w;
        float s2 = xv.x * w2.x + xv.y * w2.y + xv.z * w2.z + xv.w * w2.w;
        float s3 = xv.x * w3.x + xv.y * w3.y + xv.z * w3.z + xv.w * w3.w;
        float v = reduce4_heads(s0, s1, s2, s3, lane);
        if (lane < 4)
            ((float*)&g_scores[start + n])[lane] = (v + b_l) * tinv;
    }
    __syncthreads();

    float4 m = make_float4(-INFINITY, -INFINITY, -INFINITY, -INFINITY);
    for (int i = tid; i < len; i += NT) {
        float4 s = g_scores[start + i];
        m.x = fmaxf(m.x, s.x); m.y = fmaxf(m.y, s.y);
        m.z = fmaxf(m.z, s.z); m.w = fmaxf(m.w, s.w);
    }
    #pragma unroll
    for (int off = 16; off > 0; off >>= 1) {
        m.x = fmaxf(m.x, __shfl_xor_sync(0xFFFFFFFFu, m.x, off));
        m.y = fmaxf(m.y, __shfl_xor_sync(0xFFFFFFFFu, m.y, off));
        m.z = fmaxf(m.z, __shfl_xor_sync(0xFFFFFFFFu, m.z, off));
        m.w = fmaxf(m.w, __shfl_xor_sync(0xFFFFFFFFu, m.w, off));
    }
    if (lane == 0) wred[warp] = m;
    __syncthreads();
    float4 M;
    {
        float4 r0 = wred[0];
        #pragma unroll
        for (int wi = 1; wi < 8; wi++) {
            float4 t = wred[wi];
            r0.x = fmaxf(r0.x, t.x); r0.y = fmaxf(r0.y, t.y);
            r0.z = fmaxf(r0.z, t.z); r0.w = fmaxf(r0.w, t.w);
        }
        M = r0;
    }
    __syncthreads();

    float4 sum = make_float4(0.f, 0.f, 0.f, 0.f);
    for (int i = tid; i < len; i += NT) {
        float4 s = g_scores[start + i];
        sum.x += __expf(s.x - M.x); sum.y += __expf(s.y - M.y);
        sum.z += __expf(s.z - M.z); sum.w += __expf(s.w - M.w);
    }
    #pragma unroll
    for (int off = 16; off > 0; off >>= 1) {
        sum.x += __shfl_xor_sync(0xFFFFFFFFu, sum.x, off);
        sum.y += __shfl_xor_sync(0xFFFFFFFFu, sum.y, off);
        sum.z += __shfl_xor_sync(0xFFFFFFFFu, sum.z, off);
        sum.w += __shfl_xor_sync(0xFFFFFFFFu, sum.w, off);
    }
    if (lane == 0) wred[warp] = sum;
    __syncthreads();
    float4 R;
    {
        float4 r0 = wred[0];
        #pragma unroll
        for (int wi = 1; wi < 8; wi++) {
            float4 t = wred[wi];
            r0.x += t.x; r0.y += t.y; r0.z += t.z; r0.w += t.w;
        }
        R.x = 1.0f / r0.x; R.y = 1.0f / r0.y;
        R.z = 1.0f / r0.z; R.w = 1.0f / r0.w;
    }

    float4 acc = make_float4(0.f, 0.f, 0.f, 0.f);
    for (int c = 0; c < len; c += ROWS_CAP) {
        int cl = min(ROWS_CAP, len - c);
        __syncthreads();
        if (tid < cl) {
            float4 s = g_scores[start + c + tid];
            float a0 = __expf(s.x - M.x) * R.x;
            float a1 = __expf(s.y - M.y) * R.y;
            float a2 = __expf(s.z - M.z) * R.z;
            float a3 = __expf(s.w - M.w) * R.w;
            size_t p = (size_t)start + c + tid;
            out_attn[p]                 = a0;
            out_attn[(size_t)N + p]     = a1;
            out_attn[2 * (size_t)N + p] = a2;
            out_attn[3 * (size_t)N + p] = a3;
            w_s[tid] = 0.25f * (a0 + a1 + a2 + a3);
        }
        __syncthreads();
        for (int j = warp; j < cl; j += 8) {
            float wj = w_s[j];
            float4 v = xg4[(c + j) * 32 + lane];
            acc.x += wj * v.x; acc.y += wj * v.y;
            acc.z += wj * v.z; acc.w += wj * v.w;
        }
    }
    __syncthreads();
    pool4[warp * 32 + lane] = acc;
    __syncthreads();
    if (warp == 0) {
        float4 r = pool4[lane];
        #pragma unroll
        for (int p = 1; p < 8; p++) {
            float4 t = pool4[p * 32 + lane];
            r.x += t.x; r.y += t.y; r.z += t.z; r.w += t.w;
        }
        ((float4*)(out_pooled + (size_t)b * D))[lane] = r;
    }
}

// ---------------------------------------------------------------------------
extern "C" void kernel_launch(void* const* d_in, const int* in_sizes, int n_in,
                              void* d_out, int out_size)
{
    const float* x    = (const float*)d_in[0];
    const void*  ids  = d_in[1];
    const float* W    = (const float*)d_in[2];
    const float* bias = (const float*)d_in[3];
    const float* temp = (const float*)d_in[4];

    int N = in_sizes[1];
    int B = (out_size - H * N) / D;
    if (B < 1) B = 1;
    if (B > BMAX) B = BMAX;

    float* out_pooled = (float*)d_out;                   // [B, D]
    float* out_attn   = (float*)d_out + (size_t)B * D;   // [H, N]

    const int SMEM = (ROWS_CAP * 4 + ROWS_CAP + 8 * 32 * 4 + 8 * 4) * 4;

    k_bounds<<<(B + 256) / 256, 256>>>(ids, N, B);
    k_fused<<<B, NT, SMEM>>>(x, W, bias, temp, out_pooled, out_attn, N);
}